// round 1
// baseline (speedup 1.0000x reference)
#include <cuda_runtime.h>
#include <math.h>

#define D 768
#define T 197
#define NB 32
#define NH 12
#define HD 64
#define NLAYER 12
#define BT (NB * T)          // 6304
#define NPATCH (NB * 196)    // 6272

// -------- scratch (device globals; no allocation allowed) --------
__device__ float g_patches[NPATCH * D];          // 19.3 MB
__device__ float g_h[BT * D];                    // 19.4 MB
__device__ float g_y[BT * D];                    // 19.4 MB
__device__ float g_qkv[BT * 3 * D];              // 58.1 MB
__device__ float g_att[NB * NH * T * T];         // 59.6 MB
__device__ float g_o[BT * D];                    // 19.4 MB
__device__ float g_mlp[BT * 4 * D];              // 77.5 MB
__device__ float g_y0[NB * D];

// ---------------- patch gather ----------------
__global__ __launch_bounds__(256) void gather_patches(const float* __restrict__ x) {
    int idx = blockIdx.x * blockDim.x + threadIdx.x;
    if (idx >= NPATCH * D) return;
    int col = idx % D;
    int row = idx / D;
    int b = row / 196, p = row % 196;
    int gy = p / 14, gx = p % 14;
    int c = col / 256;
    int r2 = col % 256;
    int py = r2 / 16, px = r2 % 16;
    g_patches[idx] = x[((size_t)(b * 3 + c) * 224 + gy * 16 + py) * 224 + gx * 16 + px];
}

__global__ __launch_bounds__(256) void fill_cls(const float* __restrict__ cls) {
    int idx = blockIdx.x * blockDim.x + threadIdx.x;
    if (idx >= NB * D) return;
    int b = idx / D, d = idx % D;
    g_h[(size_t)(b * T) * D + d] = cls[d];
}

// ---------------- generic SGEMM: C[M,N] = A[M,K] @ W[N,K]^T + bias ----------------
// MODE 0: bias only. MODE 1: bias + exact GELU. MODE 2: bias + residual (extra).
// MODE 3: patch-embed scatter: out row (b*197+1+p), + pos_embed (extra).
__device__ __forceinline__ float gelu_exact(float v) {
    return 0.5f * v * (1.0f + erff(v * 0.70710678118654752f));
}

template <int MODE>
__global__ __launch_bounds__(256) void gemm64(
    const float* __restrict__ A, const float* __restrict__ W,
    const float* __restrict__ bias, float* __restrict__ C,
    int M, int N, int K, const float* __restrict__ extra) {
    __shared__ float As[16][64];
    __shared__ float Bs[16][64];
    int bm = blockIdx.y * 64, bn = blockIdx.x * 64;
    int tid = threadIdx.x;
    int tx = tid & 15, ty = tid >> 4;
    float acc[4][4] = {};

    for (int k0 = 0; k0 < K; k0 += 16) {
#pragma unroll
        for (int i = 0; i < 4; i++) {
            int idx = tid + i * 256;
            int kk = idx & 15, mm = idx >> 4;
            int gr = bm + mm;
            As[kk][mm] = (gr < M) ? A[(size_t)gr * K + k0 + kk] : 0.0f;
            int gc = bn + mm;
            Bs[kk][mm] = (gc < N) ? W[(size_t)gc * K + k0 + kk] : 0.0f;
        }
        __syncthreads();
#pragma unroll
        for (int kk = 0; kk < 16; kk++) {
            float4 a4 = *(const float4*)&As[kk][ty * 4];
            float4 b4 = *(const float4*)&Bs[kk][tx * 4];
            float av[4] = {a4.x, a4.y, a4.z, a4.w};
            float bv[4] = {b4.x, b4.y, b4.z, b4.w};
#pragma unroll
            for (int i = 0; i < 4; i++)
#pragma unroll
                for (int j = 0; j < 4; j++) acc[i][j] += av[i] * bv[j];
        }
        __syncthreads();
    }

#pragma unroll
    for (int i = 0; i < 4; i++) {
        int row = bm + ty * 4 + i;
        if (row >= M) continue;
#pragma unroll
        for (int j = 0; j < 4; j++) {
            int col = bn + tx * 4 + j;
            if (col >= N) continue;
            float v = acc[i][j] + bias[col];
            if (MODE == 1) v = gelu_exact(v);
            if (MODE == 2) v += extra[(size_t)row * N + col];
            if (MODE == 3) {
                int b = row / 196, p = row % 196;
                C[((size_t)(b * T + 1 + p)) * N + col] = v + extra[(size_t)p * N + col];
            } else {
                C[(size_t)row * N + col] = v;
            }
        }
    }
}

// ---------------- LayerNorm (block per row, D=768) ----------------
__global__ __launch_bounds__(256) void layernorm(
    const float* __restrict__ in, long in_stride,
    const float* __restrict__ w, const float* __restrict__ b,
    float* __restrict__ out, long out_stride) {
    const float* xr = in + (size_t)blockIdx.x * in_stride;
    float* yr = out + (size_t)blockIdx.x * out_stride;
    int t = threadIdx.x;
    __shared__ float rs[256], rq[256];
    float s = 0.f, sq = 0.f;
    for (int i = t; i < D; i += 256) {
        float v = xr[i];
        s += v;
        sq += v * v;
    }
    rs[t] = s;
    rq[t] = sq;
    __syncthreads();
    for (int o = 128; o > 0; o >>= 1) {
        if (t < o) { rs[t] += rs[t + o]; rq[t] += rq[t + o]; }
        __syncthreads();
    }
    float mean = rs[0] * (1.0f / D);
    float var = rq[0] * (1.0f / D) - mean * mean;
    float inv = rsqrtf(var + 1e-5f);
    for (int i = t; i < D; i += 256)
        yr[i] = (xr[i] - mean) * inv * w[i] + b[i];
}

// ---------------- attention: scores = (Q K^T) * sqrt(HD) ----------------
__global__ __launch_bounds__(256) void attn_scores(const float* __restrict__ qkv) {
    int bh = blockIdx.z;
    int b = bh / NH, h = bh % NH;
    int qt = blockIdx.y * 32, kt = blockIdx.x * 32;
    __shared__ float Qs[32][65];
    __shared__ float Ks[32][65];
    int tid = threadIdx.x;
    for (int idx = tid; idx < 2048; idx += 256) {
        int r = idx >> 6, d = idx & 63;
        int q = qt + r, k = kt + r;
        Qs[r][d] = (q < T) ? qkv[(size_t)(b * T + q) * (3 * D) + h * HD + d] : 0.f;
        Ks[r][d] = (k < T) ? qkv[(size_t)(b * T + k) * (3 * D) + D + h * HD + d] : 0.f;
    }
    __syncthreads();
    int tx = tid & 31, ty = tid >> 5;  // ty 0..7
    float acc[4] = {};
#pragma unroll 8
    for (int d = 0; d < 64; d++) {
        float kv = Ks[tx][d];
#pragma unroll
        for (int i = 0; i < 4; i++) acc[i] += Qs[ty * 4 + i][d] * kv;
    }
#pragma unroll
    for (int i = 0; i < 4; i++) {
        int q = qt + ty * 4 + i, k = kt + tx;
        if (q < T && k < T)
            g_att[((size_t)bh * T + q) * T + k] = acc[i] * 8.0f;  // *sqrt(64), faithful
    }
}

// ---------------- softmax over last dim (197), block per row ----------------
__global__ __launch_bounds__(256) void softmax_rows() {
    size_t row = blockIdx.x;
    float* p = g_att + row * T;
    int t = threadIdx.x;
    __shared__ float red[256];
    float v = (t < T) ? p[t] : -1e30f;
    red[t] = v;
    __syncthreads();
    for (int o = 128; o > 0; o >>= 1) {
        if (t < o) red[t] = fmaxf(red[t], red[t + o]);
        __syncthreads();
    }
    float mx = red[0];
    __syncthreads();
    float e = (t < T) ? __expf(v - mx) : 0.f;
    red[t] = e;
    __syncthreads();
    for (int o = 128; o > 0; o >>= 1) {
        if (t < o) red[t] += red[t + o];
        __syncthreads();
    }
    float inv = 1.0f / red[0];
    if (t < T) p[t] = e * inv;
}

// ---------------- O = att @ V, written as [B*T, D] at head offset ----------------
__global__ __launch_bounds__(256) void attn_av(const float* __restrict__ qkv) {
    int bh = blockIdx.y;
    int b = bh / NH, h = bh % NH;
    int qt = blockIdx.x * 32;
    __shared__ float As[32][33];
    __shared__ float Vs[32][65];
    int tid = threadIdx.x;
    int tx = tid & 63, ty = tid >> 6;  // tx: d 0..63, ty 0..3
    float acc[8] = {};
    for (int kt = 0; kt < T; kt += 32) {
        for (int idx = tid; idx < 1024; idx += 256) {
            int r = idx >> 5, c = idx & 31;
            int q = qt + r, k = kt + c;
            As[r][c] = (q < T && k < T) ? g_att[((size_t)bh * T + q) * T + k] : 0.f;
        }
        for (int idx = tid; idx < 2048; idx += 256) {
            int c = idx >> 6, d = idx & 63;
            int k = kt + c;
            Vs[c][d] = (k < T) ? qkv[(size_t)(b * T + k) * (3 * D) + 2 * D + h * HD + d] : 0.f;
        }
        __syncthreads();
#pragma unroll
        for (int kk = 0; kk < 32; kk++) {
            float vv = Vs[kk][tx];
#pragma unroll
            for (int i = 0; i < 8; i++) acc[i] += As[ty + 4 * i][kk] * vv;
        }
        __syncthreads();
    }
#pragma unroll
    for (int i = 0; i < 8; i++) {
        int q = qt + ty + 4 * i;
        if (q < T) g_o[(size_t)(b * T + q) * D + h * HD + tx] = acc[i];
    }
}

// ---------------- launch ----------------
static inline float* sym(void* p) { return (float*)p; }

extern "C" void kernel_launch(void* const* d_in, const int* in_sizes, int n_in,
                              void* d_out, int out_size) {
    const float* x        = (const float*)d_in[0];
    const float* patch_w  = (const float*)d_in[1];
    const float* patch_b  = (const float*)d_in[2];
    const float* pos      = (const float*)d_in[3];
    const float* cls      = (const float*)d_in[4];
    const float* ln1_w    = (const float*)d_in[5];
    const float* ln1_b    = (const float*)d_in[6];
    const float* qkv_w    = (const float*)d_in[7];
    const float* qkv_b    = (const float*)d_in[8];
    const float* proj_w   = (const float*)d_in[9];
    const float* proj_b   = (const float*)d_in[10];
    const float* ln2_w    = (const float*)d_in[11];
    const float* ln2_b    = (const float*)d_in[12];
    const float* fc1_w    = (const float*)d_in[13];
    const float* fc1_b    = (const float*)d_in[14];
    const float* fc2_w    = (const float*)d_in[15];
    const float* fc2_b    = (const float*)d_in[16];
    const float* ln_w     = (const float*)d_in[17];
    const float* ln_b     = (const float*)d_in[18];
    const float* head_w   = (const float*)d_in[19];
    const float* head_b   = (const float*)d_in[20];
    float* out = (float*)d_out;

    void *p_patches, *p_h, *p_y, *p_qkv, *p_o, *p_mlp, *p_y0;
    cudaGetSymbolAddress(&p_patches, g_patches);
    cudaGetSymbolAddress(&p_h, g_h);
    cudaGetSymbolAddress(&p_y, g_y);
    cudaGetSymbolAddress(&p_qkv, g_qkv);
    cudaGetSymbolAddress(&p_o, g_o);
    cudaGetSymbolAddress(&p_mlp, g_mlp);
    cudaGetSymbolAddress(&p_y0, g_y0);
    float* patches = sym(p_patches);
    float* h   = sym(p_h);
    float* y   = sym(p_y);
    float* qkv = sym(p_qkv);
    float* o   = sym(p_o);
    float* mlp = sym(p_mlp);
    float* y0  = sym(p_y0);

    // ---- embed ----
    gather_patches<<<(NPATCH * D + 255) / 256, 256>>>(x);
    fill_cls<<<(NB * D + 255) / 256, 256>>>(cls);
    gemm64<3><<<dim3(D / 64, NPATCH / 64), 256>>>(patches, patch_w, patch_b, h,
                                                  NPATCH, D, D, pos);

    const int MB = (BT + 63) / 64;  // 99

    // ---- transformer blocks ----
    for (int l = 0; l < NLAYER; l++) {
        layernorm<<<BT, 256>>>(h, D, ln1_w + l * D, ln1_b + l * D, y, D);
        gemm64<0><<<dim3(3 * D / 64, MB), 256>>>(y, qkv_w + (size_t)l * 3 * D * D,
                                                 qkv_b + (size_t)l * 3 * D, qkv,
                                                 BT, 3 * D, D, nullptr);
        attn_scores<<<dim3(7, 7, NB * NH), 256>>>(qkv);
        softmax_rows<<<NB * NH * T, 256>>>();
        attn_av<<<dim3(7, NB * NH), 256>>>(qkv);
        gemm64<2><<<dim3(D / 64, MB), 256>>>(o, proj_w + (size_t)l * D * D,
                                             proj_b + (size_t)l * D, h,
                                             BT, D, D, h);
        layernorm<<<BT, 256>>>(h, D, ln2_w + l * D, ln2_b + l * D, y, D);
        gemm64<1><<<dim3(4 * D / 64, MB), 256>>>(y, fc1_w + (size_t)l * 4 * D * D,
                                                 fc1_b + (size_t)l * 4 * D, mlp,
                                                 BT, 4 * D, D, nullptr);
        gemm64<2><<<dim3(D / 64, MB), 256>>>(mlp, fc2_w + (size_t)l * D * 4 * D,
                                             fc2_b + (size_t)l * D, h,
                                             BT, D, 4 * D, h);
    }

    // ---- final LN (token 0 only) + head ----
    layernorm<<<NB, 256>>>(h, (long)T * D, ln_w, ln_b, y0, D);
    gemm64<0><<<dim3((1000 + 63) / 64, 1), 256>>>(y0, head_w, head_b, out,
                                                  NB, 1000, D, nullptr);
}